// round 6
// baseline (speedup 1.0000x reference)
#include <cuda_runtime.h>
#include <math.h>

#define LCH 64
#define NTH 256
#define SQW 36          // q/S plane row stride in words (bank-bijective: 4g+tg)
#define SVW 68          // v plane row stride in words

// smem word offsets
#define QH0   0         // q hi plane [64][SQW] (2304 w), overlaid by S hi after GEMM1
#define QL0   2304      // q lo plane / S lo
#define KH0   4608
#define KL0   6912
#define VH0   9216      // v hi plane [32 j-pairs][SVW] (2176 w)
#define VL0   11392
#define GOFF  13568
#define SMEM_WORDS 14208
#define SMEM_BYTES (SMEM_WORDS * 4)

// split x into bf16 hi + bf16 lo planes, packed pairwise:
// word = {upper: elem1, lower: elem0}  (PTX cvt: first src -> upper)
__device__ __forceinline__ void split_pair(float x0, float x1, unsigned& hw, unsigned& lw) {
    asm("cvt.rn.bf16x2.f32 %0, %1, %2;" : "=r"(hw) : "f"(x1), "f"(x0));
    float h0 = __uint_as_float(hw << 16);
    float h1 = __uint_as_float(hw & 0xFFFF0000u);
    float r0 = x0 - h0;
    float r1 = x1 - h1;
    asm("cvt.rn.bf16x2.f32 %0, %1, %2;" : "=r"(lw) : "f"(r1), "f"(r0));
}

__device__ __forceinline__ void mma16(float* c, const unsigned* a, const unsigned* b) {
    asm("mma.sync.aligned.m16n8k16.row.col.f32.bf16.bf16.f32 "
        "{%0,%1,%2,%3}, {%4,%5,%6,%7}, {%8,%9}, {%0,%1,%2,%3};"
        : "+f"(c[0]), "+f"(c[1]), "+f"(c[2]), "+f"(c[3])
        : "r"(a[0]), "r"(a[1]), "r"(a[2]), "r"(a[3]), "r"(b[0]), "r"(b[1]));
}

__global__ void __launch_bounds__(NTH, 4) mlstm_intra_kernel(
    const float* __restrict__ q, const float* __restrict__ k,
    const float* __restrict__ v, const float* __restrict__ ig,
    const float* __restrict__ fg, float* __restrict__ out)
{
    extern __shared__ unsigned smu[];
    unsigned* QH = smu + QH0;   // also S hi after GEMM1
    unsigned* QL = smu + QL0;   // also S lo
    unsigned* KH = smu + KH0;
    unsigned* KL = smu + KL0;
    unsigned* VH = smu + VH0;
    unsigned* VL = smu + VL0;
    float* slf  = reinterpret_cast<float*>(smu + GOFF);
    float* sg   = slf + 64;
    float* sb   = slf + 128;
    float* senc = slf + 192;
    float* sa   = slf + 256;
    float* sfac = slf + 320;
    float* red  = slf + 384;     // [64][4]

    const int t    = threadIdx.x;
    const int lane = t & 31;
    const int w    = t >> 5;          // 0..7
    const int wy   = w >> 2;          // rows 32*wy .. +31
    const int wx   = w & 3;           // cols 16*wx .. +15
    const int g    = lane >> 2;       // 0..7
    const int tg   = lane & 3;        // 0..3
    const int rowA = 32 * wy;
    const int colB = 16 * wx;
    const size_t base = (size_t)blockIdx.x * (LCH * 64);
    const int grow = blockIdx.x * LCH;

    // ---- load + split q,k (row-major planes) ----
    {
        const int lr = t >> 2;            // row 0..63
        const int lq = t & 3;             // col block: 16 floats
        const float4* q4 = reinterpret_cast<const float4*>(q + base + lr * 64 + 16 * lq);
        const float4* k4 = reinterpret_cast<const float4*>(k + base + lr * 64 + 16 * lq);
        unsigned qh[8], ql[8], kh[8], kl[8];
#pragma unroll
        for (int c = 0; c < 4; ++c) {
            float4 wq = q4[c];
            float4 wk = k4[c];
            split_pair(wq.x, wq.y, qh[2 * c],     ql[2 * c]);
            split_pair(wq.z, wq.w, qh[2 * c + 1], ql[2 * c + 1]);
            split_pair(wk.x, wk.y, kh[2 * c],     kl[2 * c]);
            split_pair(wk.z, wk.w, kh[2 * c + 1], kl[2 * c + 1]);
        }
        unsigned* qhp = QH + lr * SQW + 8 * lq;
        unsigned* qlp = QL + lr * SQW + 8 * lq;
        unsigned* khp = KH + lr * SQW + 8 * lq;
        unsigned* klp = KL + lr * SQW + 8 * lq;
        *reinterpret_cast<uint4*>(qhp)     = make_uint4(qh[0], qh[1], qh[2], qh[3]);
        *reinterpret_cast<uint4*>(qhp + 4) = make_uint4(qh[4], qh[5], qh[6], qh[7]);
        *reinterpret_cast<uint4*>(qlp)     = make_uint4(ql[0], ql[1], ql[2], ql[3]);
        *reinterpret_cast<uint4*>(qlp + 4) = make_uint4(ql[4], ql[5], ql[6], ql[7]);
        *reinterpret_cast<uint4*>(khp)     = make_uint4(kh[0], kh[1], kh[2], kh[3]);
        *reinterpret_cast<uint4*>(khp + 4) = make_uint4(kh[4], kh[5], kh[6], kh[7]);
        *reinterpret_cast<uint4*>(klp)     = make_uint4(kl[0], kl[1], kl[2], kl[3]);
        *reinterpret_cast<uint4*>(klp + 4) = make_uint4(kl[4], kl[5], kl[6], kl[7]);
    }
    // ---- load + split v: word [j2][d] = {upper: V[2j2+1][d], lower: V[2j2][d]} ----
    {
        const int j2 = t >> 3;            // 0..31
        const int pt = t & 7;             // col block: 8 floats
        const float4* v0 = reinterpret_cast<const float4*>(v + base + (2 * j2) * 64 + 8 * pt);
        const float4* v1 = reinterpret_cast<const float4*>(v + base + (2 * j2 + 1) * 64 + 8 * pt);
        float4 a0 = v0[0], a1 = v0[1], b0 = v1[0], b1 = v1[1];
        float r0[8] = {a0.x, a0.y, a0.z, a0.w, a1.x, a1.y, a1.z, a1.w};
        float r1[8] = {b0.x, b0.y, b0.z, b0.w, b1.x, b1.y, b1.z, b1.w};
        unsigned vh[8], vl[8];
#pragma unroll
        for (int c = 0; c < 8; ++c)
            split_pair(r0[c], r1[c], vh[c], vl[c]);
        unsigned* vhp = VH + j2 * SVW + 8 * pt;
        unsigned* vlp = VL + j2 * SVW + 8 * pt;
        *reinterpret_cast<uint4*>(vhp)     = make_uint4(vh[0], vh[1], vh[2], vh[3]);
        *reinterpret_cast<uint4*>(vhp + 4) = make_uint4(vh[4], vh[5], vh[6], vh[7]);
        *reinterpret_cast<uint4*>(vlp)     = make_uint4(vl[0], vl[1], vl[2], vl[3]);
        *reinterpret_cast<uint4*>(vlp + 4) = make_uint4(vl[4], vl[5], vl[6], vl[7]);
    }

    // ---- gates (threads 0..63) ----
    float xi = 0.0f;
    if (t < LCH) {
        float xf = fg[grow + t];
        xi = ig[grow + t];
        slf[t] = fminf(xf, 0.0f) - log1pf(__expf(-fabsf(xf)));
    }
    __syncthreads();

    if (t < LCH) {
        float cum = 0.0f;
#pragma unroll 8
        for (int j = 0; j < LCH; ++j) {
            float lv = slf[j];
            if (j <= t) cum += lv;
        }
        float gval = xi - cum;
        sg[t] = gval;
        senc[t] = __expf(-cum);
        sb[t] = __expf(gval) * 0.125f;    // b[j] * 1/sqrt(64)
    }
    __syncthreads();

    if (t < LCH) {
        float M = -INFINITY;
#pragma unroll 8
        for (int j = 0; j < LCH; ++j) {
            float gv = sg[j];
            if (j <= t) M = fmaxf(M, gv);
        }
        sa[t] = __expf(-M);
    }
    __syncthreads();

    // ---- GEMM1: raw q.k^T via 2-term bf16 split (3 mmas per k16) ----
    float cacc[2][2][4];
#pragma unroll
    for (int mt = 0; mt < 2; ++mt)
#pragma unroll
        for (int nt = 0; nt < 2; ++nt)
#pragma unroll
            for (int e = 0; e < 4; ++e) cacc[mt][nt][e] = 0.0f;

    if (colB <= rowA + 31) {
#pragma unroll
        for (int kt = 0; kt < 4; ++kt) {
            const int kw = kt * 8;
            unsigned ah[2][4], al[2][4];
#pragma unroll
            for (int mt = 0; mt < 2; ++mt) {
                int r0 = rowA + 16 * mt + g;
                ah[mt][0] = QH[r0 * SQW + kw + tg];
                ah[mt][1] = QH[(r0 + 8) * SQW + kw + tg];
                ah[mt][2] = QH[r0 * SQW + kw + tg + 4];
                ah[mt][3] = QH[(r0 + 8) * SQW + kw + tg + 4];
                al[mt][0] = QL[r0 * SQW + kw + tg];
                al[mt][1] = QL[(r0 + 8) * SQW + kw + tg];
                al[mt][2] = QL[r0 * SQW + kw + tg + 4];
                al[mt][3] = QL[(r0 + 8) * SQW + kw + tg + 4];
            }
#pragma unroll
            for (int nt = 0; nt < 2; ++nt) {
                const int nb = colB + 8 * nt;
                if (nb <= rowA + 31) {
                    unsigned bh[2], bl[2];
                    bh[0] = KH[(nb + g) * SQW + kw + tg];
                    bh[1] = KH[(nb + g) * SQW + kw + tg + 4];
                    bl[0] = KL[(nb + g) * SQW + kw + tg];
                    bl[1] = KL[(nb + g) * SQW + kw + tg + 4];
#pragma unroll
                    for (int mt = 0; mt < 2; ++mt) {
                        if (nb <= rowA + 16 * mt + 15) {
                            mma16(cacc[mt][nt], al[mt], bh);
                            mma16(cacc[mt][nt], ah[mt], bl);
                            mma16(cacc[mt][nt], ah[mt], bh);
                        }
                    }
                }
            }
        }
    }
    __syncthreads();    // all q-plane reads done; S overlays

    // ---- epilogue: mask, scale by b[j], split+store S planes, row sums ----
    {
        float rs[4] = {0.0f, 0.0f, 0.0f, 0.0f};
#pragma unroll
        for (int mt = 0; mt < 2; ++mt) {
#pragma unroll
            for (int nt = 0; nt < 2; ++nt) {
                int r0 = rowA + 16 * mt + g;
                int jb = colB + 8 * nt + 2 * tg;
                int wq = (jb >> 1);
                float sb0 = sb[jb], sb1 = sb[jb + 1];
                float v00 = (jb     <= r0    ) ? cacc[mt][nt][0] * sb0 : 0.0f;
                float v01 = (jb + 1 <= r0    ) ? cacc[mt][nt][1] * sb1 : 0.0f;
                float v10 = (jb     <= r0 + 8) ? cacc[mt][nt][2] * sb0 : 0.0f;
                float v11 = (jb + 1 <= r0 + 8) ? cacc[mt][nt][3] * sb1 : 0.0f;
                unsigned hw, lw;
                split_pair(v00, v01, hw, lw);
                QH[r0 * SQW + wq] = hw;
                QL[r0 * SQW + wq] = lw;
                split_pair(v10, v11, hw, lw);
                QH[(r0 + 8) * SQW + wq] = hw;
                QL[(r0 + 8) * SQW + wq] = lw;
                rs[2 * mt]     += v00 + v01;
                rs[2 * mt + 1] += v10 + v11;
            }
        }
#pragma unroll
        for (int e = 0; e < 4; ++e) {
            rs[e] += __shfl_xor_sync(0xffffffffu, rs[e], 1);
            rs[e] += __shfl_xor_sync(0xffffffffu, rs[e], 2);
        }
        if (tg == 0) {
#pragma unroll
            for (int mt = 0; mt < 2; ++mt) {
                red[(rowA + 16 * mt + g) * 4 + wx]     = rs[2 * mt];
                red[(rowA + 16 * mt + 8 + g) * 4 + wx] = rs[2 * mt + 1];
            }
        }
    }
    __syncthreads();

    // ---- normalizer (threads 0..63) ----
    if (t < LCH) {
        float rsum = (red[t * 4] + red[t * 4 + 1]) + (red[t * 4 + 2] + red[t * 4 + 3]);
        float t1 = fmaxf(fabsf(rsum), senc[t]);
        float a_ = sa[t];
        sfac[t] = a_ / fmaf(a_, t1, 1e-6f);
    }
    __syncthreads();

    // ---- GEMM2: H = S.V (skip k-tiles above the diagonal) ----
    float c2[2][2][4];
#pragma unroll
    for (int mt = 0; mt < 2; ++mt)
#pragma unroll
        for (int nt = 0; nt < 2; ++nt)
#pragma unroll
            for (int e = 0; e < 4; ++e) c2[mt][nt][e] = 0.0f;

#pragma unroll
    for (int kt = 0; kt < 4; ++kt) {
        const int kb = 16 * kt;
        if (kb <= rowA + 31) {
            const int kw = kt * 8;
            unsigned ah[2][4], al[2][4];
#pragma unroll
            for (int mt = 0; mt < 2; ++mt) {
                int r0 = rowA + 16 * mt + g;
                ah[mt][0] = QH[r0 * SQW + kw + tg];        // S hi plane
                ah[mt][1] = QH[(r0 + 8) * SQW + kw + tg];
                ah[mt][2] = QH[r0 * SQW + kw + tg + 4];
                ah[mt][3] = QH[(r0 + 8) * SQW + kw + tg + 4];
                al[mt][0] = QL[r0 * SQW + kw + tg];
                al[mt][1] = QL[(r0 + 8) * SQW + kw + tg];
                al[mt][2] = QL[r0 * SQW + kw + tg + 4];
                al[mt][3] = QL[(r0 + 8) * SQW + kw + tg + 4];
            }
#pragma unroll
            for (int nt = 0; nt < 2; ++nt) {
                const int nb = colB + 8 * nt;
                unsigned bh[2], bl[2];
                bh[0] = VH[(kw + tg) * SVW + nb + g];
                bh[1] = VH[(kw + tg + 4) * SVW + nb + g];
                bl[0] = VL[(kw + tg) * SVW + nb + g];
                bl[1] = VL[(kw + tg + 4) * SVW + nb + g];
#pragma unroll
                for (int mt = 0; mt < 2; ++mt) {
                    mma16(c2[mt][nt], al[mt], bh);
                    mma16(c2[mt][nt], ah[mt], bl);
                    mma16(c2[mt][nt], ah[mt], bh);
                }
            }
        }
    }

    // ---- scaled output straight from fragments ----
#pragma unroll
    for (int mt = 0; mt < 2; ++mt) {
        int r0 = rowA + 16 * mt + g;
        float f0 = sfac[r0], f1 = sfac[r0 + 8];
#pragma unroll
        for (int nt = 0; nt < 2; ++nt) {
            int jb = colB + 8 * nt + 2 * tg;
            *reinterpret_cast<float2*>(out + base + r0 * 64 + jb) =
                make_float2(c2[mt][nt][0] * f0, c2[mt][nt][1] * f0);
            *reinterpret_cast<float2*>(out + base + (r0 + 8) * 64 + jb) =
                make_float2(c2[mt][nt][2] * f1, c2[mt][nt][3] * f1);
        }
    }
}

extern "C" void kernel_launch(void* const* d_in, const int* in_sizes, int n_in,
                              void* d_out, int out_size)
{
    const float* q  = (const float*)d_in[0];
    const float* k  = (const float*)d_in[1];
    const float* v  = (const float*)d_in[2];
    const float* ig = (const float*)d_in[3];
    const float* fg = (const float*)d_in[4];
    float* out = (float*)d_out;

    int nchunks = in_sizes[0] / (LCH * 64);   // 2048

    cudaFuncSetAttribute(mlstm_intra_kernel,
                         cudaFuncAttributeMaxDynamicSharedMemorySize, SMEM_BYTES);
    mlstm_intra_kernel<<<nchunks, NTH, SMEM_BYTES>>>(q, k, v, ig, fg, out);
}